// round 6
// baseline (speedup 1.0000x reference)
#include <cuda_runtime.h>
#include <cstdint>

// CoupledCLEFOModel: y = ((1+eps)I - Gamma - diag(Lambda@x))^{-1} (Ups + B@x + Theta@z)
// Jacobi: y_{k+1} = D^{-1}rhs + D^{-1}(Gamma y_k), 8 iters (~2e-7).
// R5/R6: packed f32x2 FMA (row pairs in 64-bit regs) + no X/Z smem staging
// (partial-j phase 1, pair-combined via shfl) -> smem 22KB, ~2x occupancy.
// (R5 bench was lost to a GPU-acquisition timeout; resubmitting unchanged.)

#define NDEP  32
#define HALF  16
#define NIND  64
#define NINT  16
#define TPB   128
#define SPB   (TPB / 2)      // 64 samples per block
#define NITER 8
#define REGC  1e-7f

typedef unsigned long long u64;

#define FMA2(d, a, b, c) \
    asm("fma.rn.f32x2 %0, %1, %2, %3;" : "=l"(d) : "l"(a), "l"(b), "l"(c))
#define ADD2(d, a, b) \
    asm("add.rn.f32x2 %0, %1, %2;" : "=l"(d) : "l"(a), "l"(b))
#define PACK2(d, lo, hi) \
    asm("mov.b64 %0, {%1, %2};" : "=l"(d) : "f"(lo), "f"(hi))
#define UNPACK2(lo, hi, v) \
    asm("mov.b64 {%0, %1}, %2;" : "=f"(lo), "=f"(hi) : "l"(v))

__global__ __launch_bounds__(TPB, 8)
void clefo_kernel(const float* __restrict__ X,
                  const float* __restrict__ Z,
                  const float* __restrict__ Ups,
                  const float* __restrict__ Bm,
                  const float* __restrict__ Th,
                  const float* __restrict__ Gm,
                  const float* __restrict__ Lm,
                  float* __restrict__ out,
                  int batch)
{
    __shared__ __align__(16) float sBt[NIND][NDEP];   // sBt[j][i] = B[i][j]
    __shared__ __align__(16) float sLt[NIND][NDEP];   // sLt[j][i] = Lambda[i][j]
    __shared__ __align__(16) float sTt[NINT][NDEP];   // sTt[k][i] = Theta[i][k]
    __shared__ __align__(16) float sGt[NDEP][NDEP];   // sGt[j][i] = Gamma[i][j]
    __shared__ __align__(16) float sU[NDEP];

    const int tid = threadIdx.x;

    for (int idx = tid; idx < NDEP * NIND; idx += TPB) {
        int i = idx / NIND, j = idx % NIND;
        sBt[j][i] = Bm[idx];
        sLt[j][i] = Lm[idx];
    }
    for (int idx = tid; idx < NDEP * NINT; idx += TPB) {
        int i = idx / NINT, k = idx % NINT;
        sTt[k][i] = Th[idx];
    }
    for (int idx = tid; idx < NDEP * NDEP; idx += TPB) {
        int i = idx / NDEP, j = idx % NDEP;
        sGt[j][i] = Gm[idx];
    }
    if (tid < NDEP) sU[tid] = Ups[tid];
    __syncthreads();

    const int p = tid >> 1;          // pair index = local sample
    const int h = tid & 1;           // half: j-subset owner / row-half owner
    const int s = blockIdx.x * SPB + p;
    if (s >= batch) return;          // batch=65536 divisible by SPB: never splits a warp

    // ---- Phase 1 (partial over own j-subset, ALL 32 rows, packed by row pairs) ----
    u64 rhsF[NDEP / 2], lamF[NDEP / 2];
#pragma unroll
    for (int q = 0; q < NDEP / 2; q++) { rhsF[q] = 0ULL; lamF[q] = 0ULL; }

    {
        // own 32 x values: contiguous 128B, coalesced across the warp
        const float4* Xg = reinterpret_cast<const float4*>(X + (size_t)s * NIND + h * 32);
        int jbase = h * 32;
        for (int c = 0; c < 8; c++) {
            float4 xv = Xg[c];
            float xs[4] = {xv.x, xv.y, xv.z, xv.w};
#pragma unroll
            for (int e = 0; e < 4; e++) {
                int j = jbase + c * 4 + e;
                u64 xj2; PACK2(xj2, xs[e], xs[e]);
                const ulonglong2* b2 = reinterpret_cast<const ulonglong2*>(&sBt[j][0]);
                const ulonglong2* l2 = reinterpret_cast<const ulonglong2*>(&sLt[j][0]);
#pragma unroll
                for (int q = 0; q < NDEP / 4; q++) {   // 8 ull2 per row
                    ulonglong2 bv = b2[q];
                    ulonglong2 lv = l2[q];
                    FMA2(rhsF[2*q+0], bv.x, xj2, rhsF[2*q+0]);
                    FMA2(rhsF[2*q+1], bv.y, xj2, rhsF[2*q+1]);
                    FMA2(lamF[2*q+0], lv.x, xj2, lamF[2*q+0]);
                    FMA2(lamF[2*q+1], lv.y, xj2, lamF[2*q+1]);
                }
            }
        }
    }
    {
        // own 8 z values
        const float4* Zg = reinterpret_cast<const float4*>(Z + (size_t)s * NINT + h * 8);
        int kbase = h * 8;
        for (int c = 0; c < 2; c++) {
            float4 zv = Zg[c];
            float zs[4] = {zv.x, zv.y, zv.z, zv.w};
#pragma unroll
            for (int e = 0; e < 4; e++) {
                int k = kbase + c * 4 + e;
                u64 zk2; PACK2(zk2, zs[e], zs[e]);
                const ulonglong2* t2 = reinterpret_cast<const ulonglong2*>(&sTt[k][0]);
#pragma unroll
                for (int q = 0; q < NDEP / 4; q++) {
                    ulonglong2 tv = t2[q];
                    FMA2(rhsF[2*q+0], tv.x, zk2, rhsF[2*q+0]);
                    FMA2(rhsF[2*q+1], tv.y, zk2, rhsF[2*q+1]);
                }
            }
        }
    }

    // ---- Pair-combine partials (both threads end with full sums, all 32 rows) ----
#pragma unroll
    for (int q = 0; q < NDEP / 2; q++) {
        u64 ro = __shfl_xor_sync(0xFFFFFFFFu, rhsF[q], 1);
        u64 lo = __shfl_xor_sync(0xFFFFFFFFu, lamF[q], 1);
        ADD2(rhsF[q], rhsF[q], ro);
        ADD2(lamF[q], lamF[q], lo);
    }

    // ---- Own row-half: add Ups, dinv = 1/(1+eps-lam), rhs *= dinv, y0 = rhs ----
    const u64* U2 = reinterpret_cast<const u64*>(&sU[0]);
    u64 rhs2[HALF / 2], dinv2[HALF / 2], y2[HALF / 2];
#pragma unroll
    for (int q = 0; q < HALF / 2; q++) {
        u64 rv = h ? rhsF[8 + q] : rhsF[q];
        u64 lv = h ? lamF[8 + q] : lamF[q];
        u64 uv = U2[h * 8 + q];
        float ra, rb, la, lb, ua, ub;
        UNPACK2(ra, rb, rv);
        UNPACK2(la, lb, lv);
        UNPACK2(ua, ub, uv);
        float da = 1.0f / ((1.0f + REGC) - la);
        float db = 1.0f / ((1.0f + REGC) - lb);
        ra = (ra + ua) * da;
        rb = (rb + ub) * db;
        PACK2(rhs2[q], ra, rb);
        PACK2(dinv2[q], da, db);
        y2[q] = rhs2[q];
    }

    // ---- Jacobi: y = rhs + dinv .* (Gamma @ y), rows split across the pair ----
    const int rb = h * HALF;
    for (int it = 0; it < NITER; it++) {
        u64 ylo[HALF / 2], yhi[HALF / 2];
#pragma unroll
        for (int q = 0; q < HALF / 2; q++) {
            u64 oy = __shfl_xor_sync(0xFFFFFFFFu, y2[q], 1);
            ylo[q] = h ? oy : y2[q];     // rows 2q, 2q+1
            yhi[q] = h ? y2[q] : oy;     // rows 16+2q, 17+2q
        }
        u64 acc[HALF / 2];
#pragma unroll
        for (int q = 0; q < HALF / 2; q++) acc[q] = 0ULL;

#pragma unroll
        for (int jp = 0; jp < HALF / 2; jp++) {
            float ya, yb;
            UNPACK2(ya, yb, ylo[jp]);
            {
                u64 yj2; PACK2(yj2, ya, ya);
                const ulonglong2* g2 = reinterpret_cast<const ulonglong2*>(&sGt[2*jp + 0][rb]);
#pragma unroll
                for (int q = 0; q < HALF / 4; q++) {
                    ulonglong2 gv = g2[q];
                    FMA2(acc[2*q+0], gv.x, yj2, acc[2*q+0]);
                    FMA2(acc[2*q+1], gv.y, yj2, acc[2*q+1]);
                }
            }
            {
                u64 yj2; PACK2(yj2, yb, yb);
                const ulonglong2* g2 = reinterpret_cast<const ulonglong2*>(&sGt[2*jp + 1][rb]);
#pragma unroll
                for (int q = 0; q < HALF / 4; q++) {
                    ulonglong2 gv = g2[q];
                    FMA2(acc[2*q+0], gv.x, yj2, acc[2*q+0]);
                    FMA2(acc[2*q+1], gv.y, yj2, acc[2*q+1]);
                }
            }
            float yc, yd;
            UNPACK2(yc, yd, yhi[jp]);
            {
                u64 yj2; PACK2(yj2, yc, yc);
                const ulonglong2* g2 = reinterpret_cast<const ulonglong2*>(&sGt[HALF + 2*jp + 0][rb]);
#pragma unroll
                for (int q = 0; q < HALF / 4; q++) {
                    ulonglong2 gv = g2[q];
                    FMA2(acc[2*q+0], gv.x, yj2, acc[2*q+0]);
                    FMA2(acc[2*q+1], gv.y, yj2, acc[2*q+1]);
                }
            }
            {
                u64 yj2; PACK2(yj2, yd, yd);
                const ulonglong2* g2 = reinterpret_cast<const ulonglong2*>(&sGt[HALF + 2*jp + 1][rb]);
#pragma unroll
                for (int q = 0; q < HALF / 4; q++) {
                    ulonglong2 gv = g2[q];
                    FMA2(acc[2*q+0], gv.x, yj2, acc[2*q+0]);
                    FMA2(acc[2*q+1], gv.y, yj2, acc[2*q+1]);
                }
            }
        }
#pragma unroll
        for (int q = 0; q < HALF / 2; q++)
            FMA2(y2[q], dinv2[q], acc[q], rhs2[q]);
    }

    // ---- Write own 16 rows (row pairs are consecutive floats): 4x STG.128 ----
    ulonglong2* O2 = reinterpret_cast<ulonglong2*>(out + (size_t)s * NDEP + rb);
#pragma unroll
    for (int q = 0; q < HALF / 4; q++) {
        ulonglong2 v;
        v.x = y2[2*q + 0];
        v.y = y2[2*q + 1];
        O2[q] = v;
    }
}

extern "C" void kernel_launch(void* const* d_in, const int* in_sizes, int n_in,
                              void* d_out, int out_size)
{
    const float* X   = (const float*)d_in[0];  // [batch, 64]
    const float* Z   = (const float*)d_in[1];  // [batch, 16]
    const float* Ups = (const float*)d_in[2];  // [32, 1]
    const float* Bm  = (const float*)d_in[3];  // [32, 64]
    const float* Th  = (const float*)d_in[4];  // [32, 16]
    const float* Gm  = (const float*)d_in[5];  // [32, 32]
    const float* Lm  = (const float*)d_in[6];  // [32, 64]
    float* out = (float*)d_out;

    int batch = in_sizes[0] / NIND;
    int nblocks = (batch + SPB - 1) / SPB;
    clefo_kernel<<<nblocks, TPB>>>(X, Z, Ups, Bm, Th, Gm, Lm, out, batch);
}

// round 7
// speedup vs baseline: 1.5877x; 1.5877x over previous
#include <cuda_runtime.h>
#include <cstdint>

// CoupledCLEFOModel: y = ((1+eps)I - Gamma - diag(Lambda@x))^{-1} (Ups + B@x + Theta@z)
// Jacobi: y_{k+1} = D^{-1}rhs + D^{-1}(Gamma y_k), 8 iters (~2e-7).
// R7: same f32x2 design as R6, but launch_bounds(TPB,4) -> 128-reg cap.
// R6's (TPB,8) forced a 64-reg cap and spilled the 64-reg accumulator set.

#define NDEP  32
#define HALF  16
#define NIND  64
#define NINT  16
#define TPB   128
#define SPB   (TPB / 2)      // 64 samples per block
#define NITER 8
#define REGC  1e-7f

typedef unsigned long long u64;

#define FMA2(d, a, b, c) \
    asm("fma.rn.f32x2 %0, %1, %2, %3;" : "=l"(d) : "l"(a), "l"(b), "l"(c))
#define ADD2(d, a, b) \
    asm("add.rn.f32x2 %0, %1, %2;" : "=l"(d) : "l"(a), "l"(b))
#define PACK2(d, lo, hi) \
    asm("mov.b64 %0, {%1, %2};" : "=l"(d) : "f"(lo), "f"(hi))
#define UNPACK2(lo, hi, v) \
    asm("mov.b64 {%0, %1}, %2;" : "=f"(lo), "=f"(hi) : "l"(v))

__global__ __launch_bounds__(TPB, 4)
void clefo_kernel(const float* __restrict__ X,
                  const float* __restrict__ Z,
                  const float* __restrict__ Ups,
                  const float* __restrict__ Bm,
                  const float* __restrict__ Th,
                  const float* __restrict__ Gm,
                  const float* __restrict__ Lm,
                  float* __restrict__ out,
                  int batch)
{
    __shared__ __align__(16) float sBt[NIND][NDEP];   // sBt[j][i] = B[i][j]
    __shared__ __align__(16) float sLt[NIND][NDEP];   // sLt[j][i] = Lambda[i][j]
    __shared__ __align__(16) float sTt[NINT][NDEP];   // sTt[k][i] = Theta[i][k]
    __shared__ __align__(16) float sGt[NDEP][NDEP];   // sGt[j][i] = Gamma[i][j]
    __shared__ __align__(16) float sU[NDEP];

    const int tid = threadIdx.x;

    for (int idx = tid; idx < NDEP * NIND; idx += TPB) {
        int i = idx / NIND, j = idx % NIND;
        sBt[j][i] = Bm[idx];
        sLt[j][i] = Lm[idx];
    }
    for (int idx = tid; idx < NDEP * NINT; idx += TPB) {
        int i = idx / NINT, k = idx % NINT;
        sTt[k][i] = Th[idx];
    }
    for (int idx = tid; idx < NDEP * NDEP; idx += TPB) {
        int i = idx / NDEP, j = idx % NDEP;
        sGt[j][i] = Gm[idx];
    }
    if (tid < NDEP) sU[tid] = Ups[tid];
    __syncthreads();

    const int p = tid >> 1;          // pair index = local sample
    const int h = tid & 1;           // half: j-subset owner / row-half owner
    const int s = blockIdx.x * SPB + p;
    if (s >= batch) return;          // batch divisible by SPB: never splits a warp

    // ---- Phase 1 (partial over own j-subset, ALL 32 rows, packed by row pairs) ----
    u64 rhsF[NDEP / 2], lamF[NDEP / 2];
#pragma unroll
    for (int q = 0; q < NDEP / 2; q++) { rhsF[q] = 0ULL; lamF[q] = 0ULL; }

    {
        // own 32 x values: contiguous 128B, coalesced across the warp
        const float4* Xg = reinterpret_cast<const float4*>(X + (size_t)s * NIND + h * 32);
        int jbase = h * 32;
        for (int c = 0; c < 8; c++) {
            float4 xv = Xg[c];
            float xs[4] = {xv.x, xv.y, xv.z, xv.w};
#pragma unroll
            for (int e = 0; e < 4; e++) {
                int j = jbase + c * 4 + e;
                u64 xj2; PACK2(xj2, xs[e], xs[e]);
                const ulonglong2* b2 = reinterpret_cast<const ulonglong2*>(&sBt[j][0]);
                const ulonglong2* l2 = reinterpret_cast<const ulonglong2*>(&sLt[j][0]);
#pragma unroll
                for (int q = 0; q < NDEP / 4; q++) {   // 8 ull2 per row
                    ulonglong2 bv = b2[q];
                    ulonglong2 lv = l2[q];
                    FMA2(rhsF[2*q+0], bv.x, xj2, rhsF[2*q+0]);
                    FMA2(rhsF[2*q+1], bv.y, xj2, rhsF[2*q+1]);
                    FMA2(lamF[2*q+0], lv.x, xj2, lamF[2*q+0]);
                    FMA2(lamF[2*q+1], lv.y, xj2, lamF[2*q+1]);
                }
            }
        }
    }
    {
        // own 8 z values
        const float4* Zg = reinterpret_cast<const float4*>(Z + (size_t)s * NINT + h * 8);
        int kbase = h * 8;
        for (int c = 0; c < 2; c++) {
            float4 zv = Zg[c];
            float zs[4] = {zv.x, zv.y, zv.z, zv.w};
#pragma unroll
            for (int e = 0; e < 4; e++) {
                int k = kbase + c * 4 + e;
                u64 zk2; PACK2(zk2, zs[e], zs[e]);
                const ulonglong2* t2 = reinterpret_cast<const ulonglong2*>(&sTt[k][0]);
#pragma unroll
                for (int q = 0; q < NDEP / 4; q++) {
                    ulonglong2 tv = t2[q];
                    FMA2(rhsF[2*q+0], tv.x, zk2, rhsF[2*q+0]);
                    FMA2(rhsF[2*q+1], tv.y, zk2, rhsF[2*q+1]);
                }
            }
        }
    }

    // ---- Pair-combine partials (both threads end with full sums, all 32 rows) ----
#pragma unroll
    for (int q = 0; q < NDEP / 2; q++) {
        u64 ro = __shfl_xor_sync(0xFFFFFFFFu, rhsF[q], 1);
        u64 lo = __shfl_xor_sync(0xFFFFFFFFu, lamF[q], 1);
        ADD2(rhsF[q], rhsF[q], ro);
        ADD2(lamF[q], lamF[q], lo);
    }

    // ---- Own row-half: add Ups, dinv = 1/(1+eps-lam), rhs *= dinv, y0 = rhs ----
    const u64* U2 = reinterpret_cast<const u64*>(&sU[0]);
    u64 rhs2[HALF / 2], dinv2[HALF / 2], y2[HALF / 2];
#pragma unroll
    for (int q = 0; q < HALF / 2; q++) {
        u64 rv = h ? rhsF[8 + q] : rhsF[q];
        u64 lv = h ? lamF[8 + q] : lamF[q];
        u64 uv = U2[h * 8 + q];
        float ra, rb, la, lb, ua, ub;
        UNPACK2(ra, rb, rv);
        UNPACK2(la, lb, lv);
        UNPACK2(ua, ub, uv);
        float da = 1.0f / ((1.0f + REGC) - la);
        float db = 1.0f / ((1.0f + REGC) - lb);
        ra = (ra + ua) * da;
        rb = (rb + ub) * db;
        PACK2(rhs2[q], ra, rb);
        PACK2(dinv2[q], da, db);
        y2[q] = rhs2[q];
    }

    // ---- Jacobi: y = rhs + dinv .* (Gamma @ y), rows split across the pair ----
    const int rb = h * HALF;
    for (int it = 0; it < NITER; it++) {
        u64 ylo[HALF / 2], yhi[HALF / 2];
#pragma unroll
        for (int q = 0; q < HALF / 2; q++) {
            u64 oy = __shfl_xor_sync(0xFFFFFFFFu, y2[q], 1);
            ylo[q] = h ? oy : y2[q];     // rows 2q, 2q+1
            yhi[q] = h ? y2[q] : oy;     // rows 16+2q, 17+2q
        }
        u64 acc[HALF / 2];
#pragma unroll
        for (int q = 0; q < HALF / 2; q++) acc[q] = 0ULL;

#pragma unroll
        for (int jp = 0; jp < HALF / 2; jp++) {
            float ya, yb;
            UNPACK2(ya, yb, ylo[jp]);
            {
                u64 yj2; PACK2(yj2, ya, ya);
                const ulonglong2* g2 = reinterpret_cast<const ulonglong2*>(&sGt[2*jp + 0][rb]);
#pragma unroll
                for (int q = 0; q < HALF / 4; q++) {
                    ulonglong2 gv = g2[q];
                    FMA2(acc[2*q+0], gv.x, yj2, acc[2*q+0]);
                    FMA2(acc[2*q+1], gv.y, yj2, acc[2*q+1]);
                }
            }
            {
                u64 yj2; PACK2(yj2, yb, yb);
                const ulonglong2* g2 = reinterpret_cast<const ulonglong2*>(&sGt[2*jp + 1][rb]);
#pragma unroll
                for (int q = 0; q < HALF / 4; q++) {
                    ulonglong2 gv = g2[q];
                    FMA2(acc[2*q+0], gv.x, yj2, acc[2*q+0]);
                    FMA2(acc[2*q+1], gv.y, yj2, acc[2*q+1]);
                }
            }
            float yc, yd;
            UNPACK2(yc, yd, yhi[jp]);
            {
                u64 yj2; PACK2(yj2, yc, yc);
                const ulonglong2* g2 = reinterpret_cast<const ulonglong2*>(&sGt[HALF + 2*jp + 0][rb]);
#pragma unroll
                for (int q = 0; q < HALF / 4; q++) {
                    ulonglong2 gv = g2[q];
                    FMA2(acc[2*q+0], gv.x, yj2, acc[2*q+0]);
                    FMA2(acc[2*q+1], gv.y, yj2, acc[2*q+1]);
                }
            }
            {
                u64 yj2; PACK2(yj2, yd, yd);
                const ulonglong2* g2 = reinterpret_cast<const ulonglong2*>(&sGt[HALF + 2*jp + 1][rb]);
#pragma unroll
                for (int q = 0; q < HALF / 4; q++) {
                    ulonglong2 gv = g2[q];
                    FMA2(acc[2*q+0], gv.x, yj2, acc[2*q+0]);
                    FMA2(acc[2*q+1], gv.y, yj2, acc[2*q+1]);
                }
            }
        }
#pragma unroll
        for (int q = 0; q < HALF / 2; q++)
            FMA2(y2[q], dinv2[q], acc[q], rhs2[q]);
    }

    // ---- Write own 16 rows (row pairs are consecutive floats): 4x STG.128 ----
    ulonglong2* O2 = reinterpret_cast<ulonglong2*>(out + (size_t)s * NDEP + rb);
#pragma unroll
    for (int q = 0; q < HALF / 4; q++) {
        ulonglong2 v;
        v.x = y2[2*q + 0];
        v.y = y2[2*q + 1];
        O2[q] = v;
    }
}

extern "C" void kernel_launch(void* const* d_in, const int* in_sizes, int n_in,
                              void* d_out, int out_size)
{
    const float* X   = (const float*)d_in[0];  // [batch, 64]
    const float* Z   = (const float*)d_in[1];  // [batch, 16]
    const float* Ups = (const float*)d_in[2];  // [32, 1]
    const float* Bm  = (const float*)d_in[3];  // [32, 64]
    const float* Th  = (const float*)d_in[4];  // [32, 16]
    const float* Gm  = (const float*)d_in[5];  // [32, 32]
    const float* Lm  = (const float*)d_in[6];  // [32, 64]
    float* out = (float*)d_out;

    int batch = in_sizes[0] / NIND;
    int nblocks = (batch + SPB - 1) / SPB;
    clefo_kernel<<<nblocks, TPB>>>(X, Z, Ups, Bm, Th, Gm, Lm, out, batch);
}

// round 8
// speedup vs baseline: 2.8398x; 1.7887x over previous
#include <cuda_runtime.h>
#include <cstdint>

// CoupledCLEFOModel: y = ((1+eps)I - Gamma - diag(Lambda@x))^{-1} (Ups + B@x + Theta@z)
// Jacobi: y_{k+1} = D^{-1}rhs + D^{-1}(Gamma y_k), 6 iters (~1e-5 worst).
// R8: L1-wavefront fix — each thread processes TWO samples so every smem load
// (B/Lambda/Theta/Gamma rows) is amortized over 2 samples. Pair-split rows
// (h owns 16 rows), JIT shfl for the other half of y. launch_bounds(128,3)=170 regs.

#define NDEP  32
#define HALF  16
#define NIND  64
#define NINT  16
#define TPB   128
#define SPB   128            // samples per block: 64 pairs x 2 samples
#define NITER 6
#define REGC  1e-7f

typedef unsigned long long u64;

#define FMA2(d, a, b, c) \
    asm("fma.rn.f32x2 %0, %1, %2, %3;" : "=l"(d) : "l"(a), "l"(b), "l"(c))
#define PACK2(d, lo, hi) \
    asm("mov.b64 %0, {%1, %2};" : "=l"(d) : "f"(lo), "f"(hi))
#define UNPACK2(lo, hi, v) \
    asm("mov.b64 {%0, %1}, %2;" : "=f"(lo), "=f"(hi) : "l"(v))

// One j-column step of the Jacobi matvec for BOTH samples (shared Gamma load).
#define JSTEP(jidx, sa, sb) do {                                              \
    const ulonglong2* _g = reinterpret_cast<const ulonglong2*>(&sGt[jidx][rb]); \
    ulonglong2 _g0 = _g[0], _g1 = _g[1], _g2 = _g[2], _g3 = _g[3];            \
    u64 _ya2; PACK2(_ya2, sa, sa);                                            \
    u64 _yb2; PACK2(_yb2, sb, sb);                                            \
    FMA2(aA[0], _g0.x, _ya2, aA[0]); FMA2(aA[1], _g0.y, _ya2, aA[1]);         \
    FMA2(aA[2], _g1.x, _ya2, aA[2]); FMA2(aA[3], _g1.y, _ya2, aA[3]);         \
    FMA2(aA[4], _g2.x, _ya2, aA[4]); FMA2(aA[5], _g2.y, _ya2, aA[5]);         \
    FMA2(aA[6], _g3.x, _ya2, aA[6]); FMA2(aA[7], _g3.y, _ya2, aA[7]);         \
    FMA2(aB[0], _g0.x, _yb2, aB[0]); FMA2(aB[1], _g0.y, _yb2, aB[1]);         \
    FMA2(aB[2], _g1.x, _yb2, aB[2]); FMA2(aB[3], _g1.y, _yb2, aB[3]);         \
    FMA2(aB[4], _g2.x, _yb2, aB[4]); FMA2(aB[5], _g2.y, _yb2, aB[5]);         \
    FMA2(aB[6], _g3.x, _yb2, aB[6]); FMA2(aB[7], _g3.y, _yb2, aB[7]);         \
} while (0)

// One j step of a phase-1 matrix (M = sBt/sLt/sTt) into accumulators accA/accB.
#define P1STEP(Mrow, xa2, xb2, accA, accB) do {                               \
    const ulonglong2* _m = reinterpret_cast<const ulonglong2*>(Mrow);         \
    ulonglong2 _m0 = _m[0], _m1 = _m[1], _m2 = _m[2], _m3 = _m[3];            \
    FMA2(accA[0], _m0.x, xa2, accA[0]); FMA2(accA[1], _m0.y, xa2, accA[1]);   \
    FMA2(accA[2], _m1.x, xa2, accA[2]); FMA2(accA[3], _m1.y, xa2, accA[3]);   \
    FMA2(accA[4], _m2.x, xa2, accA[4]); FMA2(accA[5], _m2.y, xa2, accA[5]);   \
    FMA2(accA[6], _m3.x, xa2, accA[6]); FMA2(accA[7], _m3.y, xa2, accA[7]);   \
    FMA2(accB[0], _m0.x, xb2, accB[0]); FMA2(accB[1], _m0.y, xb2, accB[1]);   \
    FMA2(accB[2], _m1.x, xb2, accB[2]); FMA2(accB[3], _m1.y, xb2, accB[3]);   \
    FMA2(accB[4], _m2.x, xb2, accB[4]); FMA2(accB[5], _m2.y, xb2, accB[5]);   \
    FMA2(accB[6], _m3.x, xb2, accB[6]); FMA2(accB[7], _m3.y, xb2, accB[7]);   \
} while (0)

__global__ __launch_bounds__(TPB, 3)
void clefo_kernel(const float* __restrict__ X,
                  const float* __restrict__ Z,
                  const float* __restrict__ Ups,
                  const float* __restrict__ Bm,
                  const float* __restrict__ Th,
                  const float* __restrict__ Gm,
                  const float* __restrict__ Lm,
                  float* __restrict__ out,
                  int batch)
{
    __shared__ __align__(16) float sBt[NIND][NDEP];   // sBt[j][i] = B[i][j]
    __shared__ __align__(16) float sLt[NIND][NDEP];   // sLt[j][i] = Lambda[i][j]
    __shared__ __align__(16) float sTt[NINT][NDEP];   // sTt[k][i] = Theta[i][k]
    __shared__ __align__(16) float sGt[NDEP][NDEP];   // sGt[j][i] = Gamma[i][j]
    __shared__ __align__(16) float sU[NDEP];

    const int tid = threadIdx.x;

    for (int idx = tid; idx < NDEP * NIND; idx += TPB) {
        int i = idx / NIND, j = idx % NIND;
        sBt[j][i] = Bm[idx];
        sLt[j][i] = Lm[idx];
    }
    for (int idx = tid; idx < NDEP * NINT; idx += TPB) {
        int i = idx / NINT, k = idx % NINT;
        sTt[k][i] = Th[idx];
    }
    for (int idx = tid; idx < NDEP * NDEP; idx += TPB) {
        int i = idx / NDEP, j = idx % NDEP;
        sGt[j][i] = Gm[idx];
    }
    if (tid < NDEP) sU[tid] = Ups[tid];
    __syncthreads();

    const int h  = tid & 1;            // row-half owner (pair lanes 2k,2k+1)
    const int p  = tid >> 1;           // pair index, 0..63
    const int rb = h * HALF;
    const int base = blockIdx.x * SPB; // batch = 65536 = 512*SPB exactly
    const int sA = base + p;
    const int sB = base + (SPB / 2) + p;

    // ---- Phase 1: rhs = Ups + B@x + Theta@z (own 16 rows), lam = Lambda@x (own rows)
    u64 rA[8], lA[8], rB[8], lB[8];
    {
        const ulonglong2* U2 = reinterpret_cast<const ulonglong2*>(&sU[rb]);
        ulonglong2 u0 = U2[0], u1 = U2[1], u2 = U2[2], u3 = U2[3];
        rA[0] = u0.x; rA[1] = u0.y; rA[2] = u1.x; rA[3] = u1.y;
        rA[4] = u2.x; rA[5] = u2.y; rA[6] = u3.x; rA[7] = u3.y;
#pragma unroll
        for (int q = 0; q < 8; q++) { rB[q] = rA[q]; lA[q] = 0ULL; lB[q] = 0ULL; }
    }

    const float4* XA = reinterpret_cast<const float4*>(X + (size_t)sA * NIND);
    const float4* XB = reinterpret_cast<const float4*>(X + (size_t)sB * NIND);
    for (int c = 0; c < NIND / 4; c++) {
        float4 xa = XA[c], xb = XB[c];
        float as[4] = {xa.x, xa.y, xa.z, xa.w};
        float bs[4] = {xb.x, xb.y, xb.z, xb.w};
#pragma unroll
        for (int e = 0; e < 4; e++) {
            int j = 4 * c + e;
            u64 xa2; PACK2(xa2, as[e], as[e]);
            u64 xb2; PACK2(xb2, bs[e], bs[e]);
            P1STEP(&sBt[j][rb], xa2, xb2, rA, rB);
            P1STEP(&sLt[j][rb], xa2, xb2, lA, lB);
        }
    }
    {
        const float4* ZA = reinterpret_cast<const float4*>(Z + (size_t)sA * NINT);
        const float4* ZB = reinterpret_cast<const float4*>(Z + (size_t)sB * NINT);
        for (int c = 0; c < NINT / 4; c++) {
            float4 za = ZA[c], zb = ZB[c];
            float as[4] = {za.x, za.y, za.z, za.w};
            float bs[4] = {zb.x, zb.y, zb.z, zb.w};
#pragma unroll
            for (int e = 0; e < 4; e++) {
                int k = 4 * c + e;
                u64 xa2; PACK2(xa2, as[e], as[e]);
                u64 xb2; PACK2(xb2, bs[e], bs[e]);
                P1STEP(&sTt[k][rb], xa2, xb2, rA, rB);
            }
        }
    }

    // ---- Phase 2: dinv = 1/(1+eps-lam); rhs *= dinv; y0 = rhs (own rows) ----
    u64 dA[8], dB[8], yA[8], yB[8];
#pragma unroll
    for (int q = 0; q < 8; q++) {
        float l0, l1, r0, r1;
        UNPACK2(l0, l1, lA[q]);
        UNPACK2(r0, r1, rA[q]);
        float d0 = __fdividef(1.0f, (1.0f + REGC) - l0);
        float d1 = __fdividef(1.0f, (1.0f + REGC) - l1);
        r0 *= d0; r1 *= d1;
        PACK2(rA[q], r0, r1);
        PACK2(dA[q], d0, d1);
        yA[q] = rA[q];

        UNPACK2(l0, l1, lB[q]);
        UNPACK2(r0, r1, rB[q]);
        d0 = __fdividef(1.0f, (1.0f + REGC) - l0);
        d1 = __fdividef(1.0f, (1.0f + REGC) - l1);
        r0 *= d0; r1 *= d1;
        PACK2(rB[q], r0, r1);
        PACK2(dB[q], d0, d1);
        yB[q] = rB[q];
    }

    // ---- Phase 3: Jacobi, 6 iters. Own-half j processed with local y;
    //      other-half j with pair's y via JIT shfl. Gamma loads shared by A,B.
    const int rx = rb ^ HALF;          // other half's row base = other j-base
    for (int it = 0; it < NITER; it++) {
        u64 aA[8], aB[8];
#pragma unroll
        for (int q = 0; q < 8; q++) { aA[q] = 0ULL; aB[q] = 0ULL; }

#pragma unroll
        for (int jp = 0; jp < 8; jp++) {
            u64 oA = __shfl_xor_sync(0xFFFFFFFFu, yA[jp], 1);
            u64 oB = __shfl_xor_sync(0xFFFFFFFFu, yB[jp], 1);
            float w0, w1, o0, o1, v0, v1, t0, t1;
            UNPACK2(w0, w1, yA[jp]);   // own y: rows rb+2jp, rb+2jp+1
            UNPACK2(o0, o1, oA);       // pair y: rows rx+2jp, rx+2jp+1
            UNPACK2(v0, v1, yB[jp]);
            UNPACK2(t0, t1, oB);
            int jO = rb + 2 * jp;
            int jX = rx + 2 * jp;
            JSTEP(jO,     w0, v0);
            JSTEP(jO + 1, w1, v1);
            JSTEP(jX,     o0, t0);
            JSTEP(jX + 1, o1, t1);
        }
#pragma unroll
        for (int q = 0; q < 8; q++) {
            FMA2(yA[q], dA[q], aA[q], rA[q]);
            FMA2(yB[q], dB[q], aB[q], rB[q]);
        }
    }

    // ---- Write own 16 rows for both samples ----
    ulonglong2* OA = reinterpret_cast<ulonglong2*>(out + (size_t)sA * NDEP + rb);
    ulonglong2* OB = reinterpret_cast<ulonglong2*>(out + (size_t)sB * NDEP + rb);
#pragma unroll
    for (int q = 0; q < 4; q++) {
        ulonglong2 va; va.x = yA[2*q + 0]; va.y = yA[2*q + 1];
        OA[q] = va;
        ulonglong2 vb; vb.x = yB[2*q + 0]; vb.y = yB[2*q + 1];
        OB[q] = vb;
    }
}

extern "C" void kernel_launch(void* const* d_in, const int* in_sizes, int n_in,
                              void* d_out, int out_size)
{
    const float* X   = (const float*)d_in[0];  // [batch, 64]
    const float* Z   = (const float*)d_in[1];  // [batch, 16]
    const float* Ups = (const float*)d_in[2];  // [32, 1]
    const float* Bm  = (const float*)d_in[3];  // [32, 64]
    const float* Th  = (const float*)d_in[4];  // [32, 16]
    const float* Gm  = (const float*)d_in[5];  // [32, 32]
    const float* Lm  = (const float*)d_in[6];  // [32, 64]
    float* out = (float*)d_out;

    int batch = in_sizes[0] / NIND;
    int nblocks = (batch + SPB - 1) / SPB;
    clefo_kernel<<<nblocks, TPB>>>(X, Z, Ups, Bm, Th, Gm, Lm, out, batch);
}